// round 1
// baseline (speedup 1.0000x reference)
#include <cuda_runtime.h>
#include <cuda_bf16.h>
#include <cstdint>

// ---------------- problem constants ----------------
#define B_   2
#define T_   1024
#define DM_  512
#define DI_  1024
#define DS_  16
#define KC_  4
#define NT_  (B_*T_)          // 2048 tokens
#define NXP_ (2*DS_ + DI_)    // 1056

// ---------------- scratch (device globals; no allocation allowed) ----------------
__device__ float g_xz [NT_ * (2*DI_)];   // (2048, 2048) fp32
__device__ float g_xc [NT_ * DI_];       // conv+silu out fp32
__device__ float g_bcd[NT_ * NXP_];      // (2048, 1056) fp32
__device__ float g_dt [NT_ * DI_];       // softplus(dt) fp32
__device__ float g_o  [NT_ * DM_];       // pre-LN output fp32

__device__ __nv_bfloat16 h_x   [NT_ * DM_];
__device__ __nv_bfloat16 h_inw [(2*DI_) * DM_];
__device__ __nv_bfloat16 h_xpw [NXP_ * DI_];
__device__ __nv_bfloat16 h_dtw [DI_ * DI_];
__device__ __nv_bfloat16 h_outw[DM_ * DI_];
__device__ __nv_bfloat16 h_xc  [NT_ * DI_];
__device__ __nv_bfloat16 h_bcd [NT_ * NXP_];
__device__ __nv_bfloat16 h_g   [NT_ * DI_];

// ---------------- fp32 -> bf16 convert ----------------
__global__ void cvt_bf16_kernel(const float* __restrict__ in, __nv_bfloat16* __restrict__ out, int n) {
    int i = blockIdx.x * blockDim.x + threadIdx.x;
    if (i < n) out[i] = __float2bfloat16(in[i]);
}

// ---------------- bf16 GEMM: C[M,N] = A[M,K] @ W[N,K]^T (+bias)(+res)(act) ----------------
// BM=128, BN=64, BK=32, 256 threads, 2-stage cp.async pipeline, ldmatrix + mma.m16n8k16
__device__ __forceinline__ uint32_t smem_u32(const void* p) {
    return (uint32_t)__cvta_generic_to_shared(p);
}

template<int ACT, bool HAS_RES, bool HAS_H>
__global__ void __launch_bounds__(256)
gemm_bf16(const __nv_bfloat16* __restrict__ A, int lda,
          const __nv_bfloat16* __restrict__ W, int ldb,
          float* __restrict__ C, int ldc,
          __nv_bfloat16* __restrict__ Ch, int ldh,
          const float* __restrict__ bias,
          const float* __restrict__ res,
          int M, int N, int K)
{
    constexpr int BM = 128, BN = 64, BK = 32, AST = BK + 8;   // pad 8 halves -> conflict-free ldsm
    __shared__ __nv_bfloat16 As[2][BM * AST];
    __shared__ __nv_bfloat16 Bs[2][BN * AST];

    const int tid  = threadIdx.x;
    const int warp = tid >> 5, lane = tid & 31;
    const int bm0 = blockIdx.y * BM, bn0 = blockIdx.x * BN;
    const int wm = (warp & 3) * 32, wn = (warp >> 2) * 32;

    float acc[2][4][4];
#pragma unroll
    for (int a = 0; a < 2; a++)
#pragma unroll
        for (int b = 0; b < 4; b++)
#pragma unroll
            for (int c = 0; c < 4; c++) acc[a][b][c] = 0.f;

    auto issue = [&](int stage, int k0) {
#pragma unroll
        for (int i = 0; i < 2; i++) {                 // A: 512 16B chunks / 256 thr
            int c = tid + i * 256;
            int row = c >> 2, cc = c & 3;
            const __nv_bfloat16* gp = A + (size_t)(bm0 + row) * lda + k0 + cc * 8;
            uint32_t sa = smem_u32(&As[stage][row * AST + cc * 8]);
            asm volatile("cp.async.cg.shared.global [%0], [%1], 16;\n" :: "r"(sa), "l"(gp));
        }
        {                                             // B: 256 chunks
            int c = tid;
            int row = c >> 2, cc = c & 3;
            bool valid = (bn0 + row) < N;
            const __nv_bfloat16* gp = W + (valid ? ((size_t)(bn0 + row) * ldb + k0 + cc * 8) : 0);
            uint32_t sa = smem_u32(&Bs[stage][row * AST + cc * 8]);
            int sz = valid ? 16 : 0;
            asm volatile("cp.async.cg.shared.global [%0], [%1], 16, %2;\n" :: "r"(sa), "l"(gp), "r"(sz));
        }
    };

    issue(0, 0);
    asm volatile("cp.async.commit_group;\n");
    const int KT = K / BK;

    for (int kt = 0; kt < KT; ++kt) {
        if (kt + 1 < KT) issue((kt + 1) & 1, (kt + 1) * BK);
        asm volatile("cp.async.commit_group;\n");
        asm volatile("cp.async.wait_group 1;\n");
        __syncthreads();
        const __nv_bfloat16* as = As[kt & 1];
        const __nv_bfloat16* bs = Bs[kt & 1];
#pragma unroll
        for (int ks = 0; ks < 2; ++ks) {
            uint32_t a[2][4], b[2][4];
#pragma unroll
            for (int am = 0; am < 2; ++am) {
                int row = wm + am * 16 + (lane & 7) + ((lane >> 3) & 1) * 8;
                int col = ks * 16 + (lane >> 4) * 8;
                uint32_t sa = smem_u32(&as[row * AST + col]);
                asm volatile("ldmatrix.sync.aligned.m8n8.x4.shared.b16 {%0,%1,%2,%3}, [%4];\n"
                             : "=r"(a[am][0]), "=r"(a[am][1]), "=r"(a[am][2]), "=r"(a[am][3]) : "r"(sa));
            }
#pragma unroll
            for (int bn = 0; bn < 2; ++bn) {
                int row = wn + bn * 16 + (lane & 7) + ((lane >> 4) & 1) * 8;
                int col = ks * 16 + ((lane >> 3) & 1) * 8;
                uint32_t sa = smem_u32(&bs[row * AST + col]);
                asm volatile("ldmatrix.sync.aligned.m8n8.x4.shared.b16 {%0,%1,%2,%3}, [%4];\n"
                             : "=r"(b[bn][0]), "=r"(b[bn][1]), "=r"(b[bn][2]), "=r"(b[bn][3]) : "r"(sa));
            }
#pragma unroll
            for (int am = 0; am < 2; ++am)
#pragma unroll
                for (int j = 0; j < 4; ++j) {
                    uint32_t b0 = b[j >> 1][(j & 1) ? 2 : 0];
                    uint32_t b1 = b[j >> 1][(j & 1) ? 3 : 1];
                    float* c = acc[am][j];
                    asm volatile(
                        "mma.sync.aligned.m16n8k16.row.col.f32.bf16.bf16.f32 "
                        "{%0,%1,%2,%3}, {%4,%5,%6,%7}, {%8,%9}, {%0,%1,%2,%3};\n"
                        : "+f"(c[0]), "+f"(c[1]), "+f"(c[2]), "+f"(c[3])
                        : "r"(a[am][0]), "r"(a[am][1]), "r"(a[am][2]), "r"(a[am][3]),
                          "r"(b0), "r"(b1));
                }
        }
        __syncthreads();
    }

    // epilogue
    const int g = lane >> 2, tg = lane & 3;
#pragma unroll
    for (int am = 0; am < 2; ++am)
#pragma unroll
        for (int j = 0; j < 4; ++j) {
            int col = bn0 + wn + j * 8 + tg * 2;
            if (col >= N) continue;
            float b0 = bias[col], b1 = bias[col + 1];
#pragma unroll
            for (int h = 0; h < 2; ++h) {   // h=0: rows g, h=1: rows g+8
                int row = bm0 + wm + am * 16 + g + h * 8;
                float v0 = acc[am][j][h * 2 + 0] + b0;
                float v1 = acc[am][j][h * 2 + 1] + b1;
                if (HAS_RES) {
                    v0 += res[(size_t)row * ldc + col];
                    v1 += res[(size_t)row * ldc + col + 1];
                }
                if (ACT == 1) { // softplus
                    v0 = (v0 > 20.f) ? v0 : log1pf(__expf(v0));
                    v1 = (v1 > 20.f) ? v1 : log1pf(__expf(v1));
                }
                float2* cp = (float2*)&C[(size_t)row * ldc + col];
                *cp = make_float2(v0, v1);
                if (HAS_H) {
                    __nv_bfloat162* hp = (__nv_bfloat162*)&Ch[(size_t)row * ldh + col];
                    *hp = __nv_bfloat162(__float2bfloat16(v0), __float2bfloat16(v1));
                }
            }
        }
}

// ---------------- causal depthwise conv (K=4) + silu ----------------
__global__ void conv_silu_kernel(const float* __restrict__ xz,
                                 const float* __restrict__ conv_w,
                                 const float* __restrict__ conv_b,
                                 float* __restrict__ xc,
                                 __nv_bfloat16* __restrict__ xch)
{
    int i = blockIdx.x * blockDim.x + threadIdx.x;     // over NT_*DI_
    if (i >= NT_ * DI_) return;
    int di = i & (DI_ - 1);
    int bt = i >> 10;
    int t  = bt & (T_ - 1);
    float a = conv_b[di];
#pragma unroll
    for (int k = 0; k < KC_; ++k) {
        int tk = t - (KC_ - 1) + k;
        if (tk >= 0) a += xz[(size_t)(bt - (KC_ - 1) + k) * (2*DI_) + di] * conv_w[di * KC_ + k];
    }
    float sv = __fdividef(a, 1.f + __expf(-a));
    xc[i]  = sv;
    xch[i] = __float2bfloat16(sv);
}

// ---------------- selective scan (replicates reference pscan numerics) + g = y*silu(z) ----------------
// block: 512 thr = 16 warps; warp handles 2 channels (16 ds lanes each); grid (DI/32, B)
__global__ void __launch_bounds__(512)
scan_kernel(const float* __restrict__ dt, const float* __restrict__ xc,
            const float* __restrict__ bcd, const float* __restrict__ xz,
            const float* __restrict__ A_log, const float* __restrict__ D_skip,
            __nv_bfloat16* __restrict__ gbuf)
{
    const int b    = blockIdx.y;
    const int warp = threadIdx.x >> 5, lane = threadIdx.x & 31;
    const int di   = blockIdx.x * 32 + warp * 2 + (lane >> 4);
    const int ds   = lane & 15;
    const float Av = -__expf(A_log[di * DS_ + ds]);
    const float Dv = D_skip[di];
    const int  base = b << 10;

    float L = 0.f, accum = 0.f;
    int t = 0;
    while (t < T_) {
        int bt = base + t;
        float dtv = dt[(size_t)bt * DI_ + di];
        float xv  = xc[(size_t)bt * DI_ + di];
        float Bv  = bcd[(size_t)bt * NXP_ + ds];
        float Cv  = bcd[(size_t)bt * NXP_ + DS_ + ds];
        float u = fmaxf(dtv * Av, -13.815511f);         // log(clip(exp(u),1e-6))
        L += u;
        float s = __expf(L);
        accum += __fdividef(dtv * Bv * xv, s + 1e-8f);
        float p = s * accum * Cv;
        p += __shfl_xor_sync(0xffffffffu, p, 8);
        p += __shfl_xor_sync(0xffffffffu, p, 4);
        p += __shfl_xor_sync(0xffffffffu, p, 2);
        p += __shfl_xor_sync(0xffffffffu, p, 1);
        if (ds == 0) {
            float zv = xz[(size_t)bt * (2*DI_) + DI_ + di];
            float y  = p + Dv * xv;
            gbuf[(size_t)bt * DI_ + di] =
                __float2bfloat16(y * __fdividef(zv, 1.f + __expf(-zv)));
        }
        ++t;
        // once every lane's s underflows to exactly 0 it stays 0 forever (L monotone down)
        if (__ballot_sync(0xffffffffu, L > -105.f) == 0) break;
    }
    // tail: h == 0 exactly in the reference too -> y = D*x_
    for (int tt = t + ds; tt < T_; tt += 16) {
        int bt = base + tt;
        float xv = xc[(size_t)bt * DI_ + di];
        float zv = xz[(size_t)bt * (2*DI_) + DI_ + di];
        float y  = Dv * xv;
        gbuf[(size_t)bt * DI_ + di] =
            __float2bfloat16(y * __fdividef(zv, 1.f + __expf(-zv)));
    }
}

// ---------------- LayerNorm over DM=512 per row ----------------
__global__ void __launch_bounds__(512)
ln_kernel(const float* __restrict__ o, const float* __restrict__ gam,
          const float* __restrict__ bet, float* __restrict__ out)
{
    const int row = blockIdx.x, tid = threadIdx.x;
    const int wid = tid >> 5, lane = tid & 31;
    float v = o[(size_t)row * DM_ + tid];
    float s = v, q = v * v;
#pragma unroll
    for (int off = 16; off > 0; off >>= 1) {
        s += __shfl_down_sync(0xffffffffu, s, off);
        q += __shfl_down_sync(0xffffffffu, q, off);
    }
    __shared__ float ss[16], qq[16];
    if (lane == 0) { ss[wid] = s; qq[wid] = q; }
    __syncthreads();
    if (wid == 0) {
        float s2 = (lane < 16) ? ss[lane] : 0.f;
        float q2 = (lane < 16) ? qq[lane] : 0.f;
#pragma unroll
        for (int off = 8; off > 0; off >>= 1) {
            s2 += __shfl_down_sync(0xffffffffu, s2, off);
            q2 += __shfl_down_sync(0xffffffffu, q2, off);
        }
        if (lane == 0) { ss[0] = s2; qq[0] = q2; }
    }
    __syncthreads();
    float mean = ss[0] * (1.f / DM_);
    float var  = qq[0] * (1.f / DM_) - mean * mean;
    out[(size_t)row * DM_ + tid] = (v - mean) * rsqrtf(var + 1e-5f) * gam[tid] + bet[tid];
}

// ---------------- host launcher ----------------
static inline void cvt(const float* in, __nv_bfloat16* out, int n) {
    cvt_bf16_kernel<<<(n + 255) / 256, 256>>>(in, out, n);
}

extern "C" void kernel_launch(void* const* d_in, const int* in_sizes, int n_in,
                              void* d_out, int out_size)
{
    const float* x      = (const float*)d_in[0];
    const float* in_w   = (const float*)d_in[1];
    const float* in_b   = (const float*)d_in[2];
    const float* conv_w = (const float*)d_in[3];
    const float* conv_b = (const float*)d_in[4];
    const float* xp_w   = (const float*)d_in[5];
    const float* xp_b   = (const float*)d_in[6];
    const float* dt_w   = (const float*)d_in[7];
    const float* dt_b   = (const float*)d_in[8];
    const float* A_log  = (const float*)d_in[9];
    const float* D_skip = (const float*)d_in[10];
    const float* out_w  = (const float*)d_in[11];
    const float* out_b  = (const float*)d_in[12];
    const float* ln_g   = (const float*)d_in[13];
    const float* ln_b   = (const float*)d_in[14];
    float* out = (float*)d_out;

    float *p_xz, *p_xc, *p_bcd, *p_dt, *p_o;
    __nv_bfloat16 *p_hx, *p_hinw, *p_hxpw, *p_hdtw, *p_houtw, *p_hxc, *p_hbcd, *p_hg;
    cudaGetSymbolAddress((void**)&p_xz,  g_xz);
    cudaGetSymbolAddress((void**)&p_xc,  g_xc);
    cudaGetSymbolAddress((void**)&p_bcd, g_bcd);
    cudaGetSymbolAddress((void**)&p_dt,  g_dt);
    cudaGetSymbolAddress((void**)&p_o,   g_o);
    cudaGetSymbolAddress((void**)&p_hx,   h_x);
    cudaGetSymbolAddress((void**)&p_hinw, h_inw);
    cudaGetSymbolAddress((void**)&p_hxpw, h_xpw);
    cudaGetSymbolAddress((void**)&p_hdtw, h_dtw);
    cudaGetSymbolAddress((void**)&p_houtw,h_outw);
    cudaGetSymbolAddress((void**)&p_hxc,  h_xc);
    cudaGetSymbolAddress((void**)&p_hbcd, h_bcd);
    cudaGetSymbolAddress((void**)&p_hg,   h_g);

    // 1) weight/activation bf16 converts
    cvt(x,     p_hx,   NT_ * DM_);
    cvt(in_w,  p_hinw, (2*DI_) * DM_);
    cvt(xp_w,  p_hxpw, NXP_ * DI_);
    cvt(dt_w,  p_hdtw, DI_ * DI_);
    cvt(out_w, p_houtw, DM_ * DI_);

    // 2) xz = x @ in_w^T + in_b   (2048 x 2048, K=512)
    gemm_bf16<0, false, false><<<dim3((2*DI_)/64, NT_/128), 256>>>(
        p_hx, DM_, p_hinw, DM_, p_xz, 2*DI_, nullptr, 0, in_b, nullptr, NT_, 2*DI_, DM_);

    // 3) depthwise causal conv + silu
    conv_silu_kernel<<<(NT_*DI_)/256, 256>>>(p_xz, conv_w, conv_b, p_xc, p_hxc);

    // 4) bcd = x_ @ xp_w^T + xp_b   (2048 x 1056, K=1024), also bf16 copy for dt GEMM
    gemm_bf16<0, false, true><<<dim3((NXP_ + 63)/64, NT_/128), 256>>>(
        p_hxc, DI_, p_hxpw, DI_, p_bcd, NXP_, p_hbcd, NXP_, xp_b, nullptr, NT_, NXP_, DI_);

    // 5) dt = softplus(bcd[:,32:] @ dt_w^T + dt_b)   (2048 x 1024, K=1024)
    gemm_bf16<1, false, false><<<dim3(DI_/64, NT_/128), 256>>>(
        p_hbcd + 2*DS_, NXP_, p_hdtw, DI_, p_dt, DI_, nullptr, 0, dt_b, nullptr, NT_, DI_, DI_);

    // 6) selective scan -> g = (sum h*C + D*x_) * silu(z)  (bf16)
    scan_kernel<<<dim3(DI_/32, B_), 512>>>(p_dt, p_xc, p_bcd, p_xz, A_log, D_skip, p_hg);

    // 7) o = g @ out_w^T + out_b + x   (2048 x 512, K=1024)
    gemm_bf16<0, true, false><<<dim3(DM_/64, NT_/128), 256>>>(
        p_hg, DI_, p_houtw, DI_, p_o, DM_, nullptr, 0, out_b, x, NT_, DM_, DI_);

    // 8) LayerNorm -> final output
    ln_kernel<<<NT_, 512>>>(p_o, ln_g, ln_b, out);
}

// round 2
// speedup vs baseline: 1.0265x; 1.0265x over previous
#include <cuda_runtime.h>
#include <cuda_bf16.h>
#include <cstdint>

// ---------------- problem constants ----------------
#define B_   2
#define T_   1024
#define DM_  512
#define DI_  1024
#define DS_  16
#define KC_  4
#define NT_  (B_*T_)          // 2048 tokens
#define NXP_ (2*DS_ + DI_)    // 1056

// ---------------- scratch (device globals; no allocation allowed) ----------------
__device__ float g_xz [NT_ * (2*DI_)];   // (2048, 2048) fp32
__device__ float g_xc [NT_ * DI_];       // conv+silu out fp32
__device__ float g_bcd[NT_ * NXP_];      // (2048, 1056) fp32
__device__ float g_dt [NT_ * DI_];       // softplus(dt) fp32
__device__ float g_o  [NT_ * DM_];       // pre-LN output fp32

__device__ __nv_bfloat16 h_x   [NT_ * DM_];
__device__ __nv_bfloat16 h_inw [(2*DI_) * DM_];
__device__ __nv_bfloat16 h_xpw [NXP_ * DI_];
__device__ __nv_bfloat16 h_dtw [DI_ * DI_];
__device__ __nv_bfloat16 h_outw[DM_ * DI_];
__device__ __nv_bfloat16 h_xc  [NT_ * DI_];
__device__ __nv_bfloat16 h_bcd [NT_ * NXP_];
__device__ __nv_bfloat16 h_g   [NT_ * DI_];

// ---------------- fused fp32 -> bf16 convert (all 5 arrays, float4) ----------------
// vec4 segment boundaries
#define CV_S0 262144    // x:     1048576 elems
#define CV_S1 524288    // in_w:  1048576
#define CV_S2 794624    // xp_w:  1081344
#define CV_S3 1056768   // dt_w:  1048576
#define CV_S4 1187840   // out_w:  524288

__global__ void __launch_bounds__(256)
cvt_all_kernel(const float* __restrict__ x,   const float* __restrict__ inw,
               const float* __restrict__ xpw, const float* __restrict__ dtw,
               const float* __restrict__ outw,
               __nv_bfloat16* __restrict__ hx,   __nv_bfloat16* __restrict__ hinw,
               __nv_bfloat16* __restrict__ hxpw, __nv_bfloat16* __restrict__ hdtw,
               __nv_bfloat16* __restrict__ houtw)
{
    int v = blockIdx.x * blockDim.x + threadIdx.x;
    if (v >= CV_S4) return;
    const float* s; __nv_bfloat16* d; int base;
    if (v < CV_S1) {
        if (v < CV_S0) { s = x;   d = hx;   base = 0; }
        else           { s = inw; d = hinw; base = CV_S0; }
    } else if (v < CV_S2) { s = xpw;  d = hxpw;  base = CV_S1; }
    else if   (v < CV_S3) { s = dtw;  d = hdtw;  base = CV_S2; }
    else                  { s = outw; d = houtw; base = CV_S3; }
    int i = v - base;
    float4 f = ((const float4*)s)[i];
    __nv_bfloat162* dp = (__nv_bfloat162*)(d + 8LL * 0 + (size_t)i * 4);
    dp[0] = __floats2bfloat162_rn(f.x, f.y);
    dp[1] = __floats2bfloat162_rn(f.z, f.w);
}

// ---------------- bf16 GEMM: C[M,N] = A[M,K] @ W[N,K]^T (+bias)(+res)(act) ----------------
// BM=128, BN=128, BK=32, 4-stage cp.async ring, 256 threads, warp tile 64x32
__device__ __forceinline__ uint32_t smem_u32(const void* p) {
    return (uint32_t)__cvta_generic_to_shared(p);
}

#define G_BM 128
#define G_BN 128
#define G_BK 32
#define G_ST 4
#define G_AST (G_BK + 8)
#define G_SMEM (G_ST * (G_BM + G_BN) * G_AST * 2)   // 81920 bytes

template<int ACT, bool HAS_RES, bool HAS_H>
__global__ void __launch_bounds__(256, 1)
gemm_bf16(const __nv_bfloat16* __restrict__ A, int lda,
          const __nv_bfloat16* __restrict__ W, int ldb,
          float* __restrict__ C, int ldc,
          __nv_bfloat16* __restrict__ Ch, int ldh,
          const float* __restrict__ bias,
          const float* __restrict__ res,
          int M, int N, int K)
{
    extern __shared__ __nv_bfloat16 sm_[];
    __nv_bfloat16* Asm = sm_;                                 // G_ST*BM*AST
    __nv_bfloat16* Bsm = sm_ + G_ST * G_BM * G_AST;           // G_ST*BN*AST

    const int tid  = threadIdx.x;
    const int warp = tid >> 5, lane = tid & 31;
    const int bm0 = blockIdx.y * G_BM, bn0 = blockIdx.x * G_BN;
    const int wm = (warp >> 2) * 64, wn = (warp & 3) * 32;

    float acc[4][4][4];
#pragma unroll
    for (int a = 0; a < 4; a++)
#pragma unroll
        for (int b = 0; b < 4; b++)
#pragma unroll
            for (int c = 0; c < 4; c++) acc[a][b][c] = 0.f;

    auto issue = [&](int st, int k0) {
        __nv_bfloat16* as = Asm + st * G_BM * G_AST;
        __nv_bfloat16* bs = Bsm + st * G_BN * G_AST;
#pragma unroll
        for (int i = 0; i < 2; i++) {                 // A: 512 16B chunks / 256 thr
            int c = tid + i * 256;
            int row = c >> 2, cc = c & 3;
            const __nv_bfloat16* gp = A + (size_t)(bm0 + row) * lda + k0 + cc * 8;
            uint32_t sa = smem_u32(&as[row * G_AST + cc * 8]);
            asm volatile("cp.async.cg.shared.global [%0], [%1], 16;\n" :: "r"(sa), "l"(gp));
        }
#pragma unroll
        for (int i = 0; i < 2; i++) {                 // B: 512 chunks
            int c = tid + i * 256;
            int row = c >> 2, cc = c & 3;
            bool valid = (bn0 + row) < N;
            const __nv_bfloat16* gp = W + (valid ? ((size_t)(bn0 + row) * ldb + k0 + cc * 8) : 0);
            uint32_t sa = smem_u32(&bs[row * G_AST + cc * 8]);
            int sz = valid ? 16 : 0;
            asm volatile("cp.async.cg.shared.global [%0], [%1], 16, %2;\n" :: "r"(sa), "l"(gp), "r"(sz));
        }
    };

    const int KT = K / G_BK;
#pragma unroll
    for (int s = 0; s < G_ST - 1; ++s) {
        if (s < KT) issue(s, s * G_BK);
        asm volatile("cp.async.commit_group;\n");
    }

    for (int kt = 0; kt < KT; ++kt) {
        asm volatile("cp.async.wait_group %0;\n" :: "n"(G_ST - 2));
        __syncthreads();
        const __nv_bfloat16* as = Asm + (kt & (G_ST - 1)) * G_BM * G_AST;
        const __nv_bfloat16* bs = Bsm + (kt & (G_ST - 1)) * G_BN * G_AST;
#pragma unroll
        for (int ks = 0; ks < 2; ++ks) {
            uint32_t a[4][4], b[2][4];
#pragma unroll
            for (int am = 0; am < 4; ++am) {
                int row = wm + am * 16 + (lane & 7) + ((lane >> 3) & 1) * 8;
                int col = ks * 16 + (lane >> 4) * 8;
                uint32_t sa = smem_u32(&as[row * G_AST + col]);
                asm volatile("ldmatrix.sync.aligned.m8n8.x4.shared.b16 {%0,%1,%2,%3}, [%4];\n"
                             : "=r"(a[am][0]), "=r"(a[am][1]), "=r"(a[am][2]), "=r"(a[am][3]) : "r"(sa));
            }
#pragma unroll
            for (int bn = 0; bn < 2; ++bn) {
                int row = wn + bn * 16 + (lane & 7) + ((lane >> 4) & 1) * 8;
                int col = ks * 16 + ((lane >> 3) & 1) * 8;
                uint32_t sa = smem_u32(&bs[row * G_AST + col]);
                asm volatile("ldmatrix.sync.aligned.m8n8.x4.shared.b16 {%0,%1,%2,%3}, [%4];\n"
                             : "=r"(b[bn][0]), "=r"(b[bn][1]), "=r"(b[bn][2]), "=r"(b[bn][3]) : "r"(sa));
            }
#pragma unroll
            for (int am = 0; am < 4; ++am)
#pragma unroll
                for (int j = 0; j < 4; ++j) {
                    uint32_t b0 = b[j >> 1][(j & 1) ? 2 : 0];
                    uint32_t b1 = b[j >> 1][(j & 1) ? 3 : 1];
                    float* c = acc[am][j];
                    asm volatile(
                        "mma.sync.aligned.m16n8k16.row.col.f32.bf16.bf16.f32 "
                        "{%0,%1,%2,%3}, {%4,%5,%6,%7}, {%8,%9}, {%0,%1,%2,%3};\n"
                        : "+f"(c[0]), "+f"(c[1]), "+f"(c[2]), "+f"(c[3])
                        : "r"(a[am][0]), "r"(a[am][1]), "r"(a[am][2]), "r"(a[am][3]),
                          "r"(b0), "r"(b1));
                }
        }
        int kn = kt + G_ST - 1;
        if (kn < KT) issue(kn & (G_ST - 1), kn * G_BK);
        asm volatile("cp.async.commit_group;\n");
    }

    // epilogue
    const int g = lane >> 2, tg = lane & 3;
#pragma unroll
    for (int am = 0; am < 4; ++am)
#pragma unroll
        for (int j = 0; j < 4; ++j) {
            int col = bn0 + wn + j * 8 + tg * 2;
            if (col >= N) continue;
            float b0 = bias[col], b1 = bias[col + 1];
#pragma unroll
            for (int h = 0; h < 2; ++h) {   // h=0: rows g, h=1: rows g+8
                int row = bm0 + wm + am * 16 + g + h * 8;
                float v0 = acc[am][j][h * 2 + 0] + b0;
                float v1 = acc[am][j][h * 2 + 1] + b1;
                if (HAS_RES) {
                    v0 += res[(size_t)row * ldc + col];
                    v1 += res[(size_t)row * ldc + col + 1];
                }
                if (ACT == 1) { // softplus
                    v0 = (v0 > 20.f) ? v0 : log1pf(__expf(v0));
                    v1 = (v1 > 20.f) ? v1 : log1pf(__expf(v1));
                }
                float2* cp = (float2*)&C[(size_t)row * ldc + col];
                *cp = make_float2(v0, v1);
                if (HAS_H) {
                    __nv_bfloat162* hp = (__nv_bfloat162*)&Ch[(size_t)row * ldh + col];
                    *hp = __nv_bfloat162(__float2bfloat16(v0), __float2bfloat16(v1));
                }
            }
        }
}

// ---------------- causal depthwise conv (K=4) + silu, x4 vectorized over channels ----------------
__global__ void __launch_bounds__(256)
conv_silu_kernel(const float* __restrict__ xz,
                 const float* __restrict__ conv_w,
                 const float* __restrict__ conv_b,
                 float* __restrict__ xc,
                 __nv_bfloat16* __restrict__ xch)
{
    int idx = blockIdx.x * blockDim.x + threadIdx.x;   // over NT_*DI_/4
    if (idx >= NT_ * DI_ / 4) return;
    int di = (idx & (DI_ / 4 - 1)) * 4;
    int bt = idx >> 8;                                  // DI_/4 = 256
    int t  = bt & (T_ - 1);

    float4 w0 = *(const float4*)&conv_w[(di + 0) * KC_];
    float4 w1 = *(const float4*)&conv_w[(di + 1) * KC_];
    float4 w2 = *(const float4*)&conv_w[(di + 2) * KC_];
    float4 w3 = *(const float4*)&conv_w[(di + 3) * KC_];
    float4 a  = *(const float4*)&conv_b[di];

    const float wk[4][4] = {{w0.x, w0.y, w0.z, w0.w},
                            {w1.x, w1.y, w1.z, w1.w},
                            {w2.x, w2.y, w2.z, w2.w},
                            {w3.x, w3.y, w3.z, w3.w}};
#pragma unroll
    for (int k = 0; k < KC_; ++k) {
        int tk = t - (KC_ - 1) + k;
        if (tk >= 0) {
            float4 xv = *(const float4*)&xz[(size_t)(bt - (KC_ - 1) + k) * (2*DI_) + di];
            a.x += xv.x * wk[0][k];
            a.y += xv.y * wk[1][k];
            a.z += xv.z * wk[2][k];
            a.w += xv.w * wk[3][k];
        }
    }
    float4 sv;
    sv.x = __fdividef(a.x, 1.f + __expf(-a.x));
    sv.y = __fdividef(a.y, 1.f + __expf(-a.y));
    sv.z = __fdividef(a.z, 1.f + __expf(-a.z));
    sv.w = __fdividef(a.w, 1.f + __expf(-a.w));
    *(float4*)&xc[(size_t)bt * DI_ + di] = sv;
    __nv_bfloat162* hp = (__nv_bfloat162*)&xch[(size_t)bt * DI_ + di];
    hp[0] = __floats2bfloat162_rn(sv.x, sv.y);
    hp[1] = __floats2bfloat162_rn(sv.z, sv.w);
}

// ---------------- selective scan (replicates reference pscan numerics) + g = y*silu(z) ----------------
__global__ void __launch_bounds__(512)
scan_kernel(const float* __restrict__ dt, const float* __restrict__ xc,
            const float* __restrict__ bcd, const float* __restrict__ xz,
            const float* __restrict__ A_log, const float* __restrict__ D_skip,
            __nv_bfloat16* __restrict__ gbuf)
{
    const int b    = blockIdx.y;
    const int warp = threadIdx.x >> 5, lane = threadIdx.x & 31;
    const int di   = blockIdx.x * 32 + warp * 2 + (lane >> 4);
    const int ds   = lane & 15;
    const float Av = -__expf(A_log[di * DS_ + ds]);
    const float Dv = D_skip[di];
    const int  base = b << 10;

    float L = 0.f, accum = 0.f;
    int t = 0;
    while (t < T_) {
        int bt = base + t;
        float dtv = dt[(size_t)bt * DI_ + di];
        float xv  = xc[(size_t)bt * DI_ + di];
        float Bv  = bcd[(size_t)bt * NXP_ + ds];
        float Cv  = bcd[(size_t)bt * NXP_ + DS_ + ds];
        float u = fmaxf(dtv * Av, -13.815511f);         // log(clip(exp(u),1e-6))
        L += u;
        float s = __expf(L);
        accum += __fdividef(dtv * Bv * xv, s + 1e-8f);
        float p = s * accum * Cv;
        p += __shfl_xor_sync(0xffffffffu, p, 8);
        p += __shfl_xor_sync(0xffffffffu, p, 4);
        p += __shfl_xor_sync(0xffffffffu, p, 2);
        p += __shfl_xor_sync(0xffffffffu, p, 1);
        if (ds == 0) {
            float zv = xz[(size_t)bt * (2*DI_) + DI_ + di];
            float y  = p + Dv * xv;
            gbuf[(size_t)bt * DI_ + di] =
                __float2bfloat16(y * __fdividef(zv, 1.f + __expf(-zv)));
        }
        ++t;
        // once every lane's s underflows to exactly 0 it stays 0 forever (L monotone down)
        if (__ballot_sync(0xffffffffu, L > -105.f) == 0) break;
    }
    // tail: h == 0 exactly in the reference too -> y = D*x_
    for (int tt = t + ds; tt < T_; tt += 16) {
        int bt = base + tt;
        float xv = xc[(size_t)bt * DI_ + di];
        float zv = xz[(size_t)bt * (2*DI_) + DI_ + di];
        float y  = Dv * xv;
        gbuf[(size_t)bt * DI_ + di] =
            __float2bfloat16(y * __fdividef(zv, 1.f + __expf(-zv)));
    }
}

// ---------------- LayerNorm over DM=512 per row ----------------
__global__ void __launch_bounds__(512)
ln_kernel(const float* __restrict__ o, const float* __restrict__ gam,
          const float* __restrict__ bet, float* __restrict__ out)
{
    const int row = blockIdx.x, tid = threadIdx.x;
    const int wid = tid >> 5, lane = tid & 31;
    float v = o[(size_t)row * DM_ + tid];
    float s = v, q = v * v;
#pragma unroll
    for (int off = 16; off > 0; off >>= 1) {
        s += __shfl_down_sync(0xffffffffu, s, off);
        q += __shfl_down_sync(0xffffffffu, q, off);
    }
    __shared__ float ss[16], qq[16];
    if (lane == 0) { ss[wid] = s; qq[wid] = q; }
    __syncthreads();
    if (wid == 0) {
        float s2 = (lane < 16) ? ss[lane] : 0.f;
        float q2 = (lane < 16) ? qq[lane] : 0.f;
#pragma unroll
        for (int off = 8; off > 0; off >>= 1) {
            s2 += __shfl_down_sync(0xffffffffu, s2, off);
            q2 += __shfl_down_sync(0xffffffffu, q2, off);
        }
        if (lane == 0) { ss[0] = s2; qq[0] = q2; }
    }
    __syncthreads();
    float mean = ss[0] * (1.f / DM_);
    float var  = qq[0] * (1.f / DM_) - mean * mean;
    out[(size_t)row * DM_ + tid] = (v - mean) * rsqrtf(var + 1e-5f) * gam[tid] + bet[tid];
}

// ---------------- host launcher ----------------
extern "C" void kernel_launch(void* const* d_in, const int* in_sizes, int n_in,
                              void* d_out, int out_size)
{
    const float* x      = (const float*)d_in[0];
    const float* in_w   = (const float*)d_in[1];
    const float* in_b   = (const float*)d_in[2];
    const float* conv_w = (const float*)d_in[3];
    const float* conv_b = (const float*)d_in[4];
    const float* xp_w   = (const float*)d_in[5];
    const float* xp_b   = (const float*)d_in[6];
    const float* dt_w   = (const float*)d_in[7];
    const float* dt_b   = (const float*)d_in[8];
    const float* A_log  = (const float*)d_in[9];
    const float* D_skip = (const float*)d_in[10];
    const float* out_w  = (const float*)d_in[11];
    const float* out_b  = (const float*)d_in[12];
    const float* ln_g   = (const float*)d_in[13];
    const float* ln_b   = (const float*)d_in[14];
    float* out = (float*)d_out;

    float *p_xz, *p_xc, *p_bcd, *p_dt, *p_o;
    __nv_bfloat16 *p_hx, *p_hinw, *p_hxpw, *p_hdtw, *p_houtw, *p_hxc, *p_hbcd, *p_hg;
    cudaGetSymbolAddress((void**)&p_xz,  g_xz);
    cudaGetSymbolAddress((void**)&p_xc,  g_xc);
    cudaGetSymbolAddress((void**)&p_bcd, g_bcd);
    cudaGetSymbolAddress((void**)&p_dt,  g_dt);
    cudaGetSymbolAddress((void**)&p_o,   g_o);
    cudaGetSymbolAddress((void**)&p_hx,   h_x);
    cudaGetSymbolAddress((void**)&p_hinw, h_inw);
    cudaGetSymbolAddress((void**)&p_hxpw, h_xpw);
    cudaGetSymbolAddress((void**)&p_hdtw, h_dtw);
    cudaGetSymbolAddress((void**)&p_houtw,h_outw);
    cudaGetSymbolAddress((void**)&p_hxc,  h_xc);
    cudaGetSymbolAddress((void**)&p_hbcd, h_bcd);
    cudaGetSymbolAddress((void**)&p_hg,   h_g);

    // allow 80KB dynamic smem for all gemm instantiations (idempotent, not captured)
    cudaFuncSetAttribute(gemm_bf16<0,false,false>, cudaFuncAttributeMaxDynamicSharedMemorySize, G_SMEM);
    cudaFuncSetAttribute(gemm_bf16<0,false,true >, cudaFuncAttributeMaxDynamicSharedMemorySize, G_SMEM);
    cudaFuncSetAttribute(gemm_bf16<1,false,false>, cudaFuncAttributeMaxDynamicSharedMemorySize, G_SMEM);
    cudaFuncSetAttribute(gemm_bf16<0,true ,false>, cudaFuncAttributeMaxDynamicSharedMemorySize, G_SMEM);

    // 1) fused fp32 -> bf16 converts
    cvt_all_kernel<<<(CV_S4 + 255) / 256, 256>>>(x, in_w, xp_w, dt_w, out_w,
                                                 p_hx, p_hinw, p_hxpw, p_hdtw, p_houtw);

    // 2) xz = x @ in_w^T + in_b   (2048 x 2048, K=512)
    gemm_bf16<0, false, false><<<dim3((2*DI_)/G_BN, NT_/G_BM), 256, G_SMEM>>>(
        p_hx, DM_, p_hinw, DM_, p_xz, 2*DI_, nullptr, 0, in_b, nullptr, NT_, 2*DI_, DM_);

    // 3) depthwise causal conv + silu
    conv_silu_kernel<<<(NT_*DI_/4 + 255) / 256, 256>>>(p_xz, conv_w, conv_b, p_xc, p_hxc);

    // 4) bcd = x_ @ xp_w^T + xp_b   (2048 x 1056, K=1024), also bf16 copy for dt GEMM
    gemm_bf16<0, false, true><<<dim3((NXP_ + G_BN - 1)/G_BN, NT_/G_BM), 256, G_SMEM>>>(
        p_hxc, DI_, p_hxpw, DI_, p_bcd, NXP_, p_hbcd, NXP_, xp_b, nullptr, NT_, NXP_, DI_);

    // 5) dt = softplus(bcd[:,32:] @ dt_w^T + dt_b)   (2048 x 1024, K=1024)
    gemm_bf16<1, false, false><<<dim3(DI_/G_BN, NT_/G_BM), 256, G_SMEM>>>(
        p_hbcd + 2*DS_, NXP_, p_hdtw, DI_, p_dt, DI_, nullptr, 0, dt_b, nullptr, NT_, DI_, DI_);

    // 6) selective scan -> g = (sum h*C + D*x_) * silu(z)  (bf16)
    scan_kernel<<<dim3(DI_/32, B_), 512>>>(p_dt, p_xc, p_bcd, p_xz, A_log, D_skip, p_hg);

    // 7) o = g @ out_w^T + out_b + x   (2048 x 512, K=1024)
    gemm_bf16<0, true, false><<<dim3(DM_/G_BN, NT_/G_BM), 256, G_SMEM>>>(
        p_hg, DI_, p_houtw, DI_, p_o, DM_, nullptr, 0, out_b, x, NT_, DM_, DI_);

    // 8) LayerNorm -> final output
    ln_kernel<<<NT_, 512>>>(p_o, ln_g, ln_b, out);
}

// round 4
// speedup vs baseline: 1.6551x; 1.6123x over previous
#include <cuda_runtime.h>
#include <cuda_bf16.h>
#include <cstdint>

// ---------------- problem constants ----------------
#define B_   2
#define T_   1024
#define DM_  512
#define DI_  1024
#define DS_  16
#define KC_  4
#define NT_  (B_*T_)          // 2048 tokens
#define NXP_ (2*DS_ + DI_)    // 1056

// ---------------- scratch (device globals; no allocation allowed) ----------------
__device__ float g_xz [NT_ * (2*DI_)];   // (2048, 2048) fp32
__device__ float g_xc [NT_ * DI_];       // conv+silu out fp32
__device__ float g_bcd[NT_ * NXP_];      // (2048, 1056) fp32
__device__ float g_dt [NT_ * DI_];       // softplus(dt) fp32
__device__ float g_o  [NT_ * DM_];       // pre-LN output fp32

__device__ __nv_bfloat16 h_x   [NT_ * DM_];
__device__ __nv_bfloat16 h_inw [(2*DI_) * DM_];
__device__ __nv_bfloat16 h_xpw [NXP_ * DI_];
__device__ __nv_bfloat16 h_dtw [DI_ * DI_];
__device__ __nv_bfloat16 h_outw[DM_ * DI_];
__device__ __nv_bfloat16 h_xc  [NT_ * DI_];
__device__ __nv_bfloat16 h_bcd [NT_ * NXP_];
__device__ __nv_bfloat16 h_g   [NT_ * DI_];

// ---------------- fused fp32 -> bf16 convert (all 5 arrays, float4) ----------------
#define CV_S0 262144    // x
#define CV_S1 524288    // in_w
#define CV_S2 794624    // xp_w
#define CV_S3 1056768   // dt_w
#define CV_S4 1187840   // out_w

__global__ void __launch_bounds__(256)
cvt_all_kernel(const float* __restrict__ x,   const float* __restrict__ inw,
               const float* __restrict__ xpw, const float* __restrict__ dtw,
               const float* __restrict__ outw,
               __nv_bfloat16* __restrict__ hx,   __nv_bfloat16* __restrict__ hinw,
               __nv_bfloat16* __restrict__ hxpw, __nv_bfloat16* __restrict__ hdtw,
               __nv_bfloat16* __restrict__ houtw)
{
    int v = blockIdx.x * blockDim.x + threadIdx.x;
    if (v >= CV_S4) return;
    const float* s; __nv_bfloat16* d; int base;
    if (v < CV_S1) {
        if (v < CV_S0) { s = x;   d = hx;   base = 0; }
        else           { s = inw; d = hinw; base = CV_S0; }
    } else if (v < CV_S2) { s = xpw;  d = hxpw;  base = CV_S1; }
    else if   (v < CV_S3) { s = dtw;  d = hdtw;  base = CV_S2; }
    else                  { s = outw; d = houtw; base = CV_S3; }
    int i = v - base;
    float4 f = ((const float4*)s)[i];
    __nv_bfloat162* dp = (__nv_bfloat162*)(d + (size_t)i * 4);
    dp[0] = __floats2bfloat162_rn(f.x, f.y);
    dp[1] = __floats2bfloat162_rn(f.z, f.w);
}

// ---------------- bf16 GEMM: C[M,N] = A[M,K] @ W[N,K]^T (+bias)(+res)(act) ----------------
// BN=128, BK=64, 3-stage cp.async ring, 256 threads, register double-buffered frags.
// AM=4 -> BM=128 (warp tile 64x32); AM=2 -> BM=64 (warp tile 32x32)
__device__ __forceinline__ uint32_t smem_u32(const void* p) {
    return (uint32_t)__cvta_generic_to_shared(p);
}

#define G_BN 128
#define G_BK 64
#define G_ST 3
#define G_AST (G_BK + 8)
#define G_SMEM_AM(AM) (G_ST * ((AM)*32 + G_BN) * G_AST * 2)

template<int ACT, bool HAS_RES, bool HAS_H, int AM>
__global__ void __launch_bounds__(256, 1)
gemm_bf16(const __nv_bfloat16* __restrict__ A, int lda,
          const __nv_bfloat16* __restrict__ W, int ldb,
          float* __restrict__ C, int ldc,
          __nv_bfloat16* __restrict__ Ch, int ldh,
          const float* __restrict__ bias,
          const float* __restrict__ res,
          int M, int N, int K)
{
    constexpr int BM = AM * 32;
    extern __shared__ __nv_bfloat16 sm_[];
    __nv_bfloat16* Asm = sm_;
    __nv_bfloat16* Bsm = sm_ + G_ST * BM * G_AST;

    const int tid  = threadIdx.x;
    const int warp = tid >> 5, lane = tid & 31;
    const int bm0 = blockIdx.y * BM, bn0 = blockIdx.x * G_BN;
    const int wm = (warp >> 2) * (AM * 16), wn = (warp & 3) * 32;

    float acc[AM][4][4];
#pragma unroll
    for (int a = 0; a < AM; a++)
#pragma unroll
        for (int b = 0; b < 4; b++)
#pragma unroll
            for (int c = 0; c < 4; c++) acc[a][b][c] = 0.f;

    auto issue = [&](int st, int k0) {
        __nv_bfloat16* as = Asm + st * BM * G_AST;
        __nv_bfloat16* bs = Bsm + st * G_BN * G_AST;
#pragma unroll
        for (int i = 0; i < BM * 8 / 256; i++) {          // A: BM rows x 8 16B-chunks
            int c = tid + i * 256;
            int row = c >> 3, cc = c & 7;
            const __nv_bfloat16* gp = A + (size_t)(bm0 + row) * lda + k0 + cc * 8;
            uint32_t sa = smem_u32(&as[row * G_AST + cc * 8]);
            asm volatile("cp.async.cg.shared.global [%0], [%1], 16;\n" :: "r"(sa), "l"(gp));
        }
#pragma unroll
        for (int i = 0; i < 4; i++) {                     // B: 128 rows x 8 chunks
            int c = tid + i * 256;
            int row = c >> 3, cc = c & 7;
            bool valid = (bn0 + row) < N;
            const __nv_bfloat16* gp = W + (valid ? ((size_t)(bn0 + row) * ldb + k0 + cc * 8) : 0);
            uint32_t sa = smem_u32(&bs[row * G_AST + cc * 8]);
            int sz = valid ? 16 : 0;
            asm volatile("cp.async.cg.shared.global [%0], [%1], 16, %2;\n" :: "r"(sa), "l"(gp), "r"(sz));
        }
    };

    const int KT = K / G_BK;
#pragma unroll
    for (int s = 0; s < G_ST - 1; ++s) {
        issue(s, s * G_BK);
        asm volatile("cp.async.commit_group;\n");
    }

    int st = 0;
    for (int kt = 0; kt < KT; ++kt) {
        asm volatile("cp.async.wait_group %0;\n" :: "n"(G_ST - 2));
        __syncthreads();
        const __nv_bfloat16* as = Asm + st * BM * G_AST;
        const __nv_bfloat16* bs = Bsm + st * G_BN * G_AST;

        // start next tile's loads ASAP (targets the stage read at kt-1; barrier made it safe)
        int kn = kt + G_ST - 1;
        int stn = st + G_ST - 1; if (stn >= G_ST) stn -= G_ST;
        if (kn < KT) issue(stn, kn * G_BK);
        asm volatile("cp.async.commit_group;\n");
        if (++st == G_ST) st = 0;

        uint32_t af[2][AM][4], bf[2][2][4];
        auto ldsA = [&](uint32_t (&f)[AM][4], int ks) {
#pragma unroll
            for (int am = 0; am < AM; ++am) {
                int row = wm + am * 16 + (lane & 7) + ((lane >> 3) & 1) * 8;
                int col = ks * 16 + (lane >> 4) * 8;
                uint32_t sa = smem_u32(&as[row * G_AST + col]);
                asm volatile("ldmatrix.sync.aligned.m8n8.x4.shared.b16 {%0,%1,%2,%3}, [%4];\n"
                             : "=r"(f[am][0]), "=r"(f[am][1]), "=r"(f[am][2]), "=r"(f[am][3]) : "r"(sa));
            }
        };
        auto ldsB = [&](uint32_t (&f)[2][4], int ks) {
#pragma unroll
            for (int bn = 0; bn < 2; ++bn) {
                int row = wn + bn * 16 + (lane & 7) + ((lane >> 4) & 1) * 8;
                int col = ks * 16 + ((lane >> 3) & 1) * 8;
                uint32_t sa = smem_u32(&bs[row * G_AST + col]);
                asm volatile("ldmatrix.sync.aligned.m8n8.x4.shared.b16 {%0,%1,%2,%3}, [%4];\n"
                             : "=r"(f[bn][0]), "=r"(f[bn][1]), "=r"(f[bn][2]), "=r"(f[bn][3]) : "r"(sa));
            }
        };

        ldsA(af[0], 0); ldsB(bf[0], 0);
#pragma unroll
        for (int ks = 0; ks < 4; ++ks) {
            const int cur = ks & 1, nxt = cur ^ 1;
            if (ks < 3) { ldsA(af[nxt], ks + 1); ldsB(bf[nxt], ks + 1); }
#pragma unroll
            for (int am = 0; am < AM; ++am)
#pragma unroll
                for (int j = 0; j < 4; ++j) {
                    uint32_t b0 = bf[cur][j >> 1][(j & 1) ? 2 : 0];
                    uint32_t b1 = bf[cur][j >> 1][(j & 1) ? 3 : 1];
                    float* c = acc[am][j];
                    asm volatile(
                        "mma.sync.aligned.m16n8k16.row.col.f32.bf16.bf16.f32 "
                        "{%0,%1,%2,%3}, {%4,%5,%6,%7}, {%8,%9}, {%0,%1,%2,%3};\n"
                        : "+f"(c[0]), "+f"(c[1]), "+f"(c[2]), "+f"(c[3])
                        : "r"(af[cur][am][0]), "r"(af[cur][am][1]), "r"(af[cur][am][2]), "r"(af[cur][am][3]),
                          "r"(b0), "r"(b1));
                }
        }
    }

    // epilogue
    const int g = lane >> 2, tg = lane & 3;
#pragma unroll
    for (int am = 0; am < AM; ++am)
#pragma unroll
        for (int j = 0; j < 4; ++j) {
            int col = bn0 + wn + j * 8 + tg * 2;
            if (col >= N) continue;
            float b0 = bias[col], b1 = bias[col + 1];
#pragma unroll
            for (int h = 0; h < 2; ++h) {
                int row = bm0 + wm + am * 16 + g + h * 8;
                float v0 = acc[am][j][h * 2 + 0] + b0;
                float v1 = acc[am][j][h * 2 + 1] + b1;
                if (HAS_RES) {
                    v0 += res[(size_t)row * ldc + col];
                    v1 += res[(size_t)row * ldc + col + 1];
                }
                if (ACT == 1) { // softplus
                    v0 = (v0 > 20.f) ? v0 : log1pf(__expf(v0));
                    v1 = (v1 > 20.f) ? v1 : log1pf(__expf(v1));
                }
                float2* cp = (float2*)&C[(size_t)row * ldc + col];
                *cp = make_float2(v0, v1);
                if (HAS_H) {
                    __nv_bfloat162* hp = (__nv_bfloat162*)&Ch[(size_t)row * ldh + col];
                    *hp = __nv_bfloat162(__float2bfloat16(v0), __float2bfloat16(v1));
                }
            }
        }
}

// ---------------- causal depthwise conv (K=4) + silu + g-prepass ----------------
// also writes h_g = (D*x_) * silu(z)  (scan later overwrites the non-decayed prefix)
__global__ void __launch_bounds__(256)
conv_silu_kernel(const float* __restrict__ xz,
                 const float* __restrict__ conv_w,
                 const float* __restrict__ conv_b,
                 const float* __restrict__ D_skip,
                 float* __restrict__ xc,
                 __nv_bfloat16* __restrict__ xch,
                 __nv_bfloat16* __restrict__ gpre)
{
    int idx = blockIdx.x * blockDim.x + threadIdx.x;   // over NT_*DI_/4
    if (idx >= NT_ * DI_ / 4) return;
    int di = (idx & (DI_ / 4 - 1)) * 4;
    int bt = idx >> 8;                                  // DI_/4 = 256
    int t  = bt & (T_ - 1);

    float4 w0 = *(const float4*)&conv_w[(di + 0) * KC_];
    float4 w1 = *(const float4*)&conv_w[(di + 1) * KC_];
    float4 w2 = *(const float4*)&conv_w[(di + 2) * KC_];
    float4 w3 = *(const float4*)&conv_w[(di + 3) * KC_];
    float4 a  = *(const float4*)&conv_b[di];

    const float wk[4][4] = {{w0.x, w0.y, w0.z, w0.w},
                            {w1.x, w1.y, w1.z, w1.w},
                            {w2.x, w2.y, w2.z, w2.w},
                            {w3.x, w3.y, w3.z, w3.w}};
#pragma unroll
    for (int k = 0; k < KC_; ++k) {
        int tk = t - (KC_ - 1) + k;
        if (tk >= 0) {
            float4 xv = *(const float4*)&xz[(size_t)(bt - (KC_ - 1) + k) * (2*DI_) + di];
            a.x += xv.x * wk[0][k];
            a.y += xv.y * wk[1][k];
            a.z += xv.z * wk[2][k];
            a.w += xv.w * wk[3][k];
        }
    }
    float4 sv;
    sv.x = __fdividef(a.x, 1.f + __expf(-a.x));
    sv.y = __fdividef(a.y, 1.f + __expf(-a.y));
    sv.z = __fdividef(a.z, 1.f + __expf(-a.z));
    sv.w = __fdividef(a.w, 1.f + __expf(-a.w));
    *(float4*)&xc[(size_t)bt * DI_ + di] = sv;
    __nv_bfloat162* hp = (__nv_bfloat162*)&xch[(size_t)bt * DI_ + di];
    hp[0] = __floats2bfloat162_rn(sv.x, sv.y);
    hp[1] = __floats2bfloat162_rn(sv.z, sv.w);

    // g-prepass: y = D*x_, g = y * silu(z)
    float4 zv = *(const float4*)&xz[(size_t)bt * (2*DI_) + DI_ + di];
    float4 Dv = *(const float4*)&D_skip[di];
    float g0 = Dv.x * sv.x * __fdividef(zv.x, 1.f + __expf(-zv.x));
    float g1 = Dv.y * sv.y * __fdividef(zv.y, 1.f + __expf(-zv.y));
    float g2 = Dv.z * sv.z * __fdividef(zv.z, 1.f + __expf(-zv.z));
    float g3 = Dv.w * sv.w * __fdividef(zv.w, 1.f + __expf(-zv.w));
    __nv_bfloat162* gp = (__nv_bfloat162*)&gpre[(size_t)bt * DI_ + di];
    gp[0] = __floats2bfloat162_rn(g0, g1);
    gp[1] = __floats2bfloat162_rn(g2, g3);
}

// ---------------- selective scan (chunked, prefetch, early-exit; no tail) ----------------
__global__ void __launch_bounds__(512)
scan_kernel(const float* __restrict__ dt, const float* __restrict__ xc,
            const float* __restrict__ bcd, const float* __restrict__ xz,
            const float* __restrict__ A_log, const float* __restrict__ D_skip,
            __nv_bfloat16* __restrict__ gbuf)
{
    const int b    = blockIdx.y;
    const int warp = threadIdx.x >> 5, lane = threadIdx.x & 31;
    const int di   = blockIdx.x * 32 + warp * 2 + (lane >> 4);
    const int ds   = lane & 15;
    const float Av = -__expf(A_log[di * DS_ + ds]);
    const float Dv = D_skip[di];
    const int  base = b << 10;

    float L = 0.f, accum = 0.f;
    for (int t0 = 0; t0 < T_; t0 += 4) {
        float dtv[4], xv[4], Bv[4], Cv[4];
#pragma unroll
        for (int j = 0; j < 4; ++j) {        // batched prefetch: MLP 16
            int bt = base + t0 + j;
            dtv[j] = dt[(size_t)bt * DI_ + di];
            xv[j]  = xc[(size_t)bt * DI_ + di];
            Bv[j]  = bcd[(size_t)bt * NXP_ + ds];
            Cv[j]  = bcd[(size_t)bt * NXP_ + DS_ + ds];
        }
#pragma unroll
        for (int j = 0; j < 4; ++j) {
            int bt = base + t0 + j;
            float u = fmaxf(dtv[j] * Av, -13.815511f);   // log(clip(exp(u),1e-6))
            L += u;
            float s = __expf(L);
            accum += __fdividef(dtv[j] * Bv[j] * xv[j], s + 1e-8f);
            float p = s * accum * Cv[j];
            p += __shfl_xor_sync(0xffffffffu, p, 8);
            p += __shfl_xor_sync(0xffffffffu, p, 4);
            p += __shfl_xor_sync(0xffffffffu, p, 2);
            p += __shfl_xor_sync(0xffffffffu, p, 1);
            if (ds == 0) {
                float zv = xz[(size_t)bt * (2*DI_) + DI_ + di];
                float y  = p + Dv * xv[j];
                gbuf[(size_t)bt * DI_ + di] =
                    __float2bfloat16(y * __fdividef(zv, 1.f + __expf(-zv)));
            }
        }
        // once all lanes have s==0 the rest equals the prepass value exactly
        if (__ballot_sync(0xffffffffu, L > -105.f) == 0) break;
    }
}

// ---------------- LayerNorm over DM=512 per row ----------------
__global__ void __launch_bounds__(512)
ln_kernel(const float* __restrict__ o, const float* __restrict__ gam,
          const float* __restrict__ bet, float* __restrict__ out)
{
    const int row = blockIdx.x, tid = threadIdx.x;
    const int wid = tid >> 5, lane = tid & 31;
    float v = o[(size_t)row * DM_ + tid];
    float s = v, q = v * v;
#pragma unroll
    for (int off = 16; off > 0; off >>= 1) {
        s += __shfl_down_sync(0xffffffffu, s, off);
        q += __shfl_down_sync(0xffffffffu, q, off);
    }
    __shared__ float ss[16], qq[16];
    if (lane == 0) { ss[wid] = s; qq[wid] = q; }
    __syncthreads();
    if (wid == 0) {
        float s2 = (lane < 16) ? ss[lane] : 0.f;
        float q2 = (lane < 16) ? qq[lane] : 0.f;
#pragma unroll
        for (int off = 8; off > 0; off >>= 1) {
            s2 += __shfl_down_sync(0xffffffffu, s2, off);
            q2 += __shfl_down_sync(0xffffffffu, q2, off);
        }
        if (lane == 0) { ss[0] = s2; qq[0] = q2; }
    }
    __syncthreads();
    float mean = ss[0] * (1.f / DM_);
    float var  = qq[0] * (1.f / DM_) - mean * mean;
    out[(size_t)row * DM_ + tid] = (v - mean) * rsqrtf(var + 1e-5f) * gam[tid] + bet[tid];
}

// ---------------- host launcher ----------------
extern "C" void kernel_launch(void* const* d_in, const int* in_sizes, int n_in,
                              void* d_out, int out_size)
{
    const float* x      = (const float*)d_in[0];
    const float* in_w   = (const float*)d_in[1];
    const float* in_b   = (const float*)d_in[2];
    const float* conv_w = (const float*)d_in[3];
    const float* conv_b = (const float*)d_in[4];
    const float* xp_w   = (const float*)d_in[5];
    const float* xp_b   = (const float*)d_in[6];
    const float* dt_w   = (const float*)d_in[7];
    const float* dt_b   = (const float*)d_in[8];
    const float* A_log  = (const float*)d_in[9];
    const float* D_skip = (const float*)d_in[10];
    const float* out_w  = (const float*)d_in[11];
    const float* out_b  = (const float*)d_in[12];
    const float* ln_g   = (const float*)d_in[13];
    const float* ln_b   = (const float*)d_in[14];
    float* out = (float*)d_out;

    float *p_xz, *p_xc, *p_bcd, *p_dt, *p_o;
    __nv_bfloat16 *p_hx, *p_hinw, *p_hxpw, *p_hdtw, *p_houtw, *p_hxc, *p_hbcd, *p_hg;
    cudaGetSymbolAddress((void**)&p_xz,  g_xz);
    cudaGetSymbolAddress((void**)&p_xc,  g_xc);
    cudaGetSymbolAddress((void**)&p_bcd, g_bcd);
    cudaGetSymbolAddress((void**)&p_dt,  g_dt);
    cudaGetSymbolAddress((void**)&p_o,   g_o);
    cudaGetSymbolAddress((void**)&p_hx,   h_x);
    cudaGetSymbolAddress((void**)&p_hinw, h_inw);
    cudaGetSymbolAddress((void**)&p_hxpw, h_xpw);
    cudaGetSymbolAddress((void**)&p_hdtw, h_dtw);
    cudaGetSymbolAddress((void**)&p_houtw,h_outw);
    cudaGetSymbolAddress((void**)&p_hxc,  h_xc);
    cudaGetSymbolAddress((void**)&p_hbcd, h_bcd);
    cudaGetSymbolAddress((void**)&p_hg,   h_g);

    cudaFuncSetAttribute(gemm_bf16<0,false,false,4>, cudaFuncAttributeMaxDynamicSharedMemorySize, G_SMEM_AM(4));
    cudaFuncSetAttribute(gemm_bf16<0,false,true ,4>, cudaFuncAttributeMaxDynamicSharedMemorySize, G_SMEM_AM(4));
    cudaFuncSetAttribute(gemm_bf16<1,false,false,4>, cudaFuncAttributeMaxDynamicSharedMemorySize, G_SMEM_AM(4));
    cudaFuncSetAttribute(gemm_bf16<0,true ,false,2>, cudaFuncAttributeMaxDynamicSharedMemorySize, G_SMEM_AM(2));

    // 1) fused fp32 -> bf16 converts
    cvt_all_kernel<<<(CV_S4 + 255) / 256, 256>>>(x, in_w, xp_w, dt_w, out_w,
                                                 p_hx, p_hinw, p_hxpw, p_hdtw, p_houtw);

    // 2) xz = x @ in_w^T + in_b   (2048 x 2048, K=512)
    gemm_bf16<0, false, false, 4><<<dim3((2*DI_)/G_BN, NT_/128), 256, G_SMEM_AM(4)>>>(
        p_hx, DM_, p_hinw, DM_, p_xz, 2*DI_, nullptr, 0, in_b, nullptr, NT_, 2*DI_, DM_);

    // 3) depthwise causal conv + silu + g-prepass
    conv_silu_kernel<<<(NT_*DI_/4 + 255) / 256, 256>>>(p_xz, conv_w, conv_b, D_skip,
                                                       p_xc, p_hxc, p_hg);

    // 4) bcd = x_ @ xp_w^T + xp_b   (2048 x 1056, K=1024), bf16 copy for dt GEMM
    gemm_bf16<0, false, true, 4><<<dim3((NXP_ + G_BN - 1)/G_BN, NT_/128), 256, G_SMEM_AM(4)>>>(
        p_hxc, DI_, p_hxpw, DI_, p_bcd, NXP_, p_hbcd, NXP_, xp_b, nullptr, NT_, NXP_, DI_);

    // 5) dt = softplus(bcd[:,32:] @ dt_w^T + dt_b)   (2048 x 1024, K=1024)
    gemm_bf16<1, false, false, 4><<<dim3(DI_/G_BN, NT_/128), 256, G_SMEM_AM(4)>>>(
        p_hbcd + 2*DS_, NXP_, p_hdtw, DI_, p_dt, DI_, nullptr, 0, dt_b, nullptr, NT_, DI_, DI_);

    // 6) selective scan -> overwrite g for the non-decayed prefix
    scan_kernel<<<dim3(DI_/32, B_), 512>>>(p_dt, p_xc, p_bcd, p_xz, A_log, D_skip, p_hg);

    // 7) o = g @ out_w^T + out_b + x   (2048 x 512, K=1024), BM=64 for 128 CTAs
    gemm_bf16<0, true, false, 2><<<dim3(DM_/G_BN, NT_/64), 256, G_SMEM_AM(2)>>>(
        p_hg, DI_, p_houtw, DI_, p_o, DM_, nullptr, 0, out_b, x, NT_, DM_, DI_);

    // 8) LayerNorm -> final output
    ln_kernel<<<NT_, 512>>>(p_o, ln_g, ln_b, out);
}

// round 6
// speedup vs baseline: 1.8344x; 1.1083x over previous
#include <cuda_runtime.h>
#include <cuda_bf16.h>
#include <cstdint>

// ---------------- problem constants ----------------
#define B_   2
#define T_   1024
#define DM_  512
#define DI_  1024
#define DS_  16
#define KC_  4
#define NT_  (B_*T_)          // 2048 tokens
#define NXP_ (2*DS_ + DI_)    // 1056

// ---------------- scratch (device globals; no allocation allowed) ----------------
__device__ float g_xz [NT_ * (2*DI_)];   // (2048, 2048) fp32
__device__ float g_xc [NT_ * DI_];       // conv+silu out fp32
__device__ float g_bcd[NT_ * NXP_];      // (2048, 1056) fp32
__device__ float g_dt [NT_ * DI_];       // softplus(dt) fp32
__device__ float g_o  [NT_ * DM_];       // pre-LN output fp32

__device__ __nv_bfloat16 h_x   [NT_ * DM_];
__device__ __nv_bfloat16 h_inw [(2*DI_) * DM_];
__device__ __nv_bfloat16 h_xpw [NXP_ * DI_];
__device__ __nv_bfloat16 h_dtw [DI_ * DI_];
__device__ __nv_bfloat16 h_outw[DM_ * DI_];
__device__ __nv_bfloat16 h_xc  [NT_ * DI_];
__device__ __nv_bfloat16 h_bcd [NT_ * NXP_];
__device__ __nv_bfloat16 h_g   [NT_ * DI_];

// ---------------- fused fp32 -> bf16 convert (all 5 arrays, float4) ----------------
#define CV_S0 262144    // x
#define CV_S1 524288    // in_w
#define CV_S2 794624    // xp_w
#define CV_S3 1056768   // dt_w
#define CV_S4 1187840   // out_w

__global__ void __launch_bounds__(256)
cvt_all_kernel(const float* __restrict__ x,   const float* __restrict__ inw,
               const float* __restrict__ xpw, const float* __restrict__ dtw,
               const float* __restrict__ outw,
               __nv_bfloat16* __restrict__ hx,   __nv_bfloat16* __restrict__ hinw,
               __nv_bfloat16* __restrict__ hxpw, __nv_bfloat16* __restrict__ hdtw,
               __nv_bfloat16* __restrict__ houtw)
{
    int v = blockIdx.x * blockDim.x + threadIdx.x;
    if (v >= CV_S4) return;
    const float* s; __nv_bfloat16* d; int base;
    if (v < CV_S1) {
        if (v < CV_S0) { s = x;   d = hx;   base = 0; }
        else           { s = inw; d = hinw; base = CV_S0; }
    } else if (v < CV_S2) { s = xpw;  d = hxpw;  base = CV_S1; }
    else if   (v < CV_S3) { s = dtw;  d = hdtw;  base = CV_S2; }
    else                  { s = outw; d = houtw; base = CV_S3; }
    int i = v - base;
    float4 f = ((const float4*)s)[i];
    __nv_bfloat162* dp = (__nv_bfloat162*)(d + (size_t)i * 4);
    dp[0] = __floats2bfloat162_rn(f.x, f.y);
    dp[1] = __floats2bfloat162_rn(f.z, f.w);
}

// ---------------- bf16 GEMM: C[M,N] = A[M,K] @ W[N,K]^T (+bias)(+res)(act) ----------------
// BN=128, BK=64, 3-stage cp.async ring, 256 threads, XOR-swizzled smem (no pad),
// 2 CTAs/SM via __launch_bounds__(256,2). AM=4 -> BM=128; AM=2 -> BM=64.
__device__ __forceinline__ uint32_t smem_u32(const void* p) {
    return (uint32_t)__cvta_generic_to_shared(p);
}

#define G_BN 128
#define G_BK 64
#define G_ST 3
// per-stage bytes: rows * 128 (64 bf16 per row, 8 chunks of 16B, XOR-swizzled)
#define G_ASTG(AM) ((AM) * 32 * 128)
#define G_BSTG     (G_BN * 128)
#define G_SMEM_AM(AM) (G_ST * (G_ASTG(AM) + G_BSTG))
// chunk-swizzled byte offset within a row
#define CSWZ(row, cc) ((uint32_t)(((cc) ^ ((row) & 7)) << 4))

template<int ACT, bool HAS_RES, bool HAS_H, int AM>
__global__ void __launch_bounds__(256, 2)
gemm_bf16(const __nv_bfloat16* __restrict__ A, int lda,
          const __nv_bfloat16* __restrict__ W, int ldb,
          float* __restrict__ C, int ldc,
          __nv_bfloat16* __restrict__ Ch, int ldh,
          const float* __restrict__ bias,
          const float* __restrict__ res,
          int M, int N, int K)
{
    constexpr int BM = AM * 32;
    extern __shared__ char sm_[];
    const uint32_t AsU = smem_u32(sm_);
    const uint32_t BsU = AsU + G_ST * G_ASTG(AM);

    const int tid  = threadIdx.x;
    const int warp = tid >> 5, lane = tid & 31;
    const int bm0 = blockIdx.y * BM, bn0 = blockIdx.x * G_BN;
    const int wm = (warp >> 2) * (AM * 16), wn = (warp & 3) * 32;

    float acc[AM][4][4];
#pragma unroll
    for (int a = 0; a < AM; a++)
#pragma unroll
        for (int b = 0; b < 4; b++)
#pragma unroll
            for (int c = 0; c < 4; c++) acc[a][b][c] = 0.f;

    auto issue = [&](int st, int k0) {
        uint32_t as = AsU + st * G_ASTG(AM);
        uint32_t bs = BsU + st * G_BSTG;
#pragma unroll
        for (int i = 0; i < BM * 8 / 256; i++) {          // A: BM rows x 8 16B-chunks
            int c = tid + i * 256;
            int row = c >> 3, cc = c & 7;
            const __nv_bfloat16* gp = A + (size_t)(bm0 + row) * lda + k0 + cc * 8;
            uint32_t sa = as + (uint32_t)(row << 7) + CSWZ(row, cc);
            asm volatile("cp.async.cg.shared.global [%0], [%1], 16;\n" :: "r"(sa), "l"(gp));
        }
#pragma unroll
        for (int i = 0; i < 4; i++) {                     // B: 128 rows x 8 chunks
            int c = tid + i * 256;
            int row = c >> 3, cc = c & 7;
            bool valid = (bn0 + row) < N;
            const __nv_bfloat16* gp = W + (valid ? ((size_t)(bn0 + row) * ldb + k0 + cc * 8) : 0);
            uint32_t sa = bs + (uint32_t)(row << 7) + CSWZ(row, cc);
            int sz = valid ? 16 : 0;
            asm volatile("cp.async.cg.shared.global [%0], [%1], 16, %2;\n" :: "r"(sa), "l"(gp), "r"(sz));
        }
    };

    const int KT = K / G_BK;
#pragma unroll
    for (int s = 0; s < G_ST - 1; ++s) {
        issue(s, s * G_BK);
        asm volatile("cp.async.commit_group;\n");
    }

    int st = 0;
    for (int kt = 0; kt < KT; ++kt) {
        asm volatile("cp.async.wait_group %0;\n" :: "n"(G_ST - 2));
        __syncthreads();
        const uint32_t as = AsU + st * G_ASTG(AM);
        const uint32_t bs = BsU + st * G_BSTG;

        // start next tile's loads ASAP (targets the stage read at kt-1; barrier made it safe)
        int kn = kt + G_ST - 1;
        int stn = st + G_ST - 1; if (stn >= G_ST) stn -= G_ST;
        if (kn < KT) issue(stn, kn * G_BK);
        asm volatile("cp.async.commit_group;\n");
        if (++st == G_ST) st = 0;

#pragma unroll
        for (int ks = 0; ks < 4; ++ks) {
            uint32_t af[AM][4], bf[2][4];
#pragma unroll
            for (int am = 0; am < AM; ++am) {
                int row = wm + am * 16 + (lane & 15);
                int ch  = ks * 2 + (lane >> 4);
                uint32_t sa = as + (uint32_t)(row << 7) + CSWZ(row, ch);
                asm volatile("ldmatrix.sync.aligned.m8n8.x4.shared.b16 {%0,%1,%2,%3}, [%4];\n"
                             : "=r"(af[am][0]), "=r"(af[am][1]), "=r"(af[am][2]), "=r"(af[am][3]) : "r"(sa));
            }
#pragma unroll
            for (int bn = 0; bn < 2; ++bn) {
                int row = wn + bn * 16 + (lane & 7) + ((lane >> 4) & 1) * 8;
                int ch  = ks * 2 + ((lane >> 3) & 1);
                uint32_t sa = bs + (uint32_t)(row << 7) + CSWZ(row, ch);
                asm volatile("ldmatrix.sync.aligned.m8n8.x4.shared.b16 {%0,%1,%2,%3}, [%4];\n"
                             : "=r"(bf[bn][0]), "=r"(bf[bn][1]), "=r"(bf[bn][2]), "=r"(bf[bn][3]) : "r"(sa));
            }
#pragma unroll
            for (int am = 0; am < AM; ++am)
#pragma unroll
                for (int j = 0; j < 4; ++j) {
                    uint32_t b0 = bf[j >> 1][(j & 1) ? 2 : 0];
                    uint32_t b1 = bf[j >> 1][(j & 1) ? 3 : 1];
                    float* c = acc[am][j];
                    asm volatile(
                        "mma.sync.aligned.m16n8k16.row.col.f32.bf16.bf16.f32 "
                        "{%0,%1,%2,%3}, {%4,%5,%6,%7}, {%8,%9}, {%0,%1,%2,%3};\n"
                        : "+f"(c[0]), "+f"(c[1]), "+f"(c[2]), "+f"(c[3])
                        : "r"(af[am][0]), "r"(af[am][1]), "r"(af[am][2]), "r"(af[am][3]),
                          "r"(b0), "r"(b1));
                }
        }
    }

    // epilogue
    const int g = lane >> 2, tg = lane & 3;
#pragma unroll
    for (int am = 0; am < AM; ++am)
#pragma unroll
        for (int j = 0; j < 4; ++j) {
            int col = bn0 + wn + j * 8 + tg * 2;
            if (col >= N) continue;
            float b0 = bias[col], b1 = bias[col + 1];
#pragma unroll
            for (int h = 0; h < 2; ++h) {
                int row = bm0 + wm + am * 16 + g + h * 8;
                float v0 = acc[am][j][h * 2 + 0] + b0;
                float v1 = acc[am][j][h * 2 + 1] + b1;
                if (HAS_RES) {
                    v0 += res[(size_t)row * ldc + col];
                    v1 += res[(size_t)row * ldc + col + 1];
                }
                if (ACT == 1) { // softplus
                    v0 = (v0 > 20.f) ? v0 : log1pf(__expf(v0));
                    v1 = (v1 > 20.f) ? v1 : log1pf(__expf(v1));
                }
                float2* cp = (float2*)&C[(size_t)row * ldc + col];
                *cp = make_float2(v0, v1);
                if (HAS_H) {
                    __nv_bfloat162* hp = (__nv_bfloat162*)&Ch[(size_t)row * ldh + col];
                    *hp = __nv_bfloat162(__float2bfloat16(v0), __float2bfloat16(v1));
                }
            }
        }
}

// ---------------- causal depthwise conv (K=4) + silu + g-prepass ----------------
__global__ void __launch_bounds__(256)
conv_silu_kernel(const float* __restrict__ xz,
                 const float* __restrict__ conv_w,
                 const float* __restrict__ conv_b,
                 const float* __restrict__ D_skip,
                 float* __restrict__ xc,
                 __nv_bfloat16* __restrict__ xch,
                 __nv_bfloat16* __restrict__ gpre)
{
    int idx = blockIdx.x * blockDim.x + threadIdx.x;   // over NT_*DI_/4
    if (idx >= NT_ * DI_ / 4) return;
    int di = (idx & (DI_ / 4 - 1)) * 4;
    int bt = idx >> 8;                                  // DI_/4 = 256
    int t  = bt & (T_ - 1);

    float4 w0 = *(const float4*)&conv_w[(di + 0) * KC_];
    float4 w1 = *(const float4*)&conv_w[(di + 1) * KC_];
    float4 w2 = *(const float4*)&conv_w[(di + 2) * KC_];
    float4 w3 = *(const float4*)&conv_w[(di + 3) * KC_];
    float4 a  = *(const float4*)&conv_b[di];

    const float wk[4][4] = {{w0.x, w0.y, w0.z, w0.w},
                            {w1.x, w1.y, w1.z, w1.w},
                            {w2.x, w2.y, w2.z, w2.w},
                            {w3.x, w3.y, w3.z, w3.w}};
#pragma unroll
    for (int k = 0; k < KC_; ++k) {
        int tk = t - (KC_ - 1) + k;
        if (tk >= 0) {
            float4 xv = *(const float4*)&xz[(size_t)(bt - (KC_ - 1) + k) * (2*DI_) + di];
            a.x += xv.x * wk[0][k];
            a.y += xv.y * wk[1][k];
            a.z += xv.z * wk[2][k];
            a.w += xv.w * wk[3][k];
        }
    }
    float4 sv;
    sv.x = __fdividef(a.x, 1.f + __expf(-a.x));
    sv.y = __fdividef(a.y, 1.f + __expf(-a.y));
    sv.z = __fdividef(a.z, 1.f + __expf(-a.z));
    sv.w = __fdividef(a.w, 1.f + __expf(-a.w));
    *(float4*)&xc[(size_t)bt * DI_ + di] = sv;
    __nv_bfloat162* hp = (__nv_bfloat162*)&xch[(size_t)bt * DI_ + di];
    hp[0] = __floats2bfloat162_rn(sv.x, sv.y);
    hp[1] = __floats2bfloat162_rn(sv.z, sv.w);

    // g-prepass: y = D*x_, g = y * silu(z)
    float4 zv = *(const float4*)&xz[(size_t)bt * (2*DI_) + DI_ + di];
    float4 Dv = *(const float4*)&D_skip[di];
    float g0 = Dv.x * sv.x * __fdividef(zv.x, 1.f + __expf(-zv.x));
    float g1 = Dv.y * sv.y * __fdividef(zv.y, 1.f + __expf(-zv.y));
    float g2 = Dv.z * sv.z * __fdividef(zv.z, 1.f + __expf(-zv.z));
    float g3 = Dv.w * sv.w * __fdividef(zv.w, 1.f + __expf(-zv.w));
    __nv_bfloat162* gp = (__nv_bfloat162*)&gpre[(size_t)bt * DI_ + di];
    gp[0] = __floats2bfloat162_rn(g0, g1);
    gp[1] = __floats2bfloat162_rn(g2, g3);
}

// ---------------- selective scan (chunked, prefetch, early-exit; no tail) ----------------
__global__ void __launch_bounds__(512)
scan_kernel(const float* __restrict__ dt, const float* __restrict__ xc,
            const float* __restrict__ bcd, const float* __restrict__ xz,
            const float* __restrict__ A_log, const float* __restrict__ D_skip,
            __nv_bfloat16* __restrict__ gbuf)
{
    const int b    = blockIdx.y;
    const int warp = threadIdx.x >> 5, lane = threadIdx.x & 31;
    const int di   = blockIdx.x * 32 + warp * 2 + (lane >> 4);
    const int ds   = lane & 15;
    const float Av = -__expf(A_log[di * DS_ + ds]);
    const float Dv = D_skip[di];
    const int  base = b << 10;

    float L = 0.f, accum = 0.f;
    for (int t0 = 0; t0 < T_; t0 += 4) {
        float dtv[4], xv[4], Bv[4], Cv[4];
#pragma unroll
        for (int j = 0; j < 4; ++j) {        // batched prefetch: MLP 16
            int bt = base + t0 + j;
            dtv[j] = dt[(size_t)bt * DI_ + di];
            xv[j]  = xc[(size_t)bt * DI_ + di];
            Bv[j]  = bcd[(size_t)bt * NXP_ + ds];
            Cv[j]  = bcd[(size_t)bt * NXP_ + DS_ + ds];
        }
#pragma unroll
        for (int j = 0; j < 4; ++j) {
            int bt = base + t0 + j;
            float u = fmaxf(dtv[j] * Av, -13.815511f);   // log(clip(exp(u),1e-6))
            L += u;
            float s = __expf(L);
            accum += __fdividef(dtv[j] * Bv[j] * xv[j], s + 1e-8f);
            float p = s * accum * Cv[j];
            p += __shfl_xor_sync(0xffffffffu, p, 8);
            p += __shfl_xor_sync(0xffffffffu, p, 4);
            p += __shfl_xor_sync(0xffffffffu, p, 2);
            p += __shfl_xor_sync(0xffffffffu, p, 1);
            if (ds == 0) {
                float zv = xz[(size_t)bt * (2*DI_) + DI_ + di];
                float y  = p + Dv * xv[j];
                gbuf[(size_t)bt * DI_ + di] =
                    __float2bfloat16(y * __fdividef(zv, 1.f + __expf(-zv)));
            }
        }
        // once all lanes have s==0 the rest equals the prepass value exactly
        if (__ballot_sync(0xffffffffu, L > -105.f) == 0) break;
    }
}

// ---------------- LayerNorm over DM=512 per row ----------------
__global__ void __launch_bounds__(512)
ln_kernel(const float* __restrict__ o, const float* __restrict__ gam,
          const float* __restrict__ bet, float* __restrict__ out)
{
    const int row = blockIdx.x, tid = threadIdx.x;
    const int wid = tid >> 5, lane = tid & 31;
    float v = o[(size_t)row * DM_ + tid];
    float s = v, q = v * v;
#pragma unroll
    for (int off = 16; off > 0; off >>= 1) {
        s += __shfl_down_sync(0xffffffffu, s, off);
        q += __shfl_down_sync(0xffffffffu, q, off);
    }
    __shared__ float ss[16], qq[16];
    if (lane == 0) { ss[wid] = s; qq[wid] = q; }
    __syncthreads();
    if (wid == 0) {
        float s2 = (lane < 16) ? ss[lane] : 0.f;
        float q2 = (lane < 16) ? qq[lane] : 0.f;
#pragma unroll
        for (int off = 8; off > 0; off >>= 1) {
            s2 += __shfl_down_sync(0xffffffffu, s2, off);
            q2 += __shfl_down_sync(0xffffffffu, q2, off);
        }
        if (lane == 0) { ss[0] = s2; qq[0] = q2; }
    }
    __syncthreads();
    float mean = ss[0] * (1.f / DM_);
    float var  = qq[0] * (1.f / DM_) - mean * mean;
    out[(size_t)row * DM_ + tid] = (v - mean) * rsqrtf(var + 1e-5f) * gam[tid] + bet[tid];
}

// ---------------- host launcher ----------------
extern "C" void kernel_launch(void* const* d_in, const int* in_sizes, int n_in,
                              void* d_out, int out_size)
{
    const float* x      = (const float*)d_in[0];
    const float* in_w   = (const float*)d_in[1];
    const float* in_b   = (const float*)d_in[2];
    const float* conv_w = (const float*)d_in[3];
    const float* conv_b = (const float*)d_in[4];
    const float* xp_w   = (const float*)d_in[5];
    const float* xp_b   = (const float*)d_in[6];
    const float* dt_w   = (const float*)d_in[7];
    const float* dt_b   = (const float*)d_in[8];
    const float* A_log  = (const float*)d_in[9];
    const float* D_skip = (const float*)d_in[10];
    const float* out_w  = (const float*)d_in[11];
    const float* out_b  = (const float*)d_in[12];
    const float* ln_g   = (const float*)d_in[13];
    const float* ln_b   = (const float*)d_in[14];
    float* out = (float*)d_out;

    float *p_xz, *p_xc, *p_bcd, *p_dt, *p_o;
    __nv_bfloat16 *p_hx, *p_hinw, *p_hxpw, *p_hdtw, *p_houtw, *p_hxc, *p_hbcd, *p_hg;
    cudaGetSymbolAddress((void**)&p_xz,  g_xz);
    cudaGetSymbolAddress((void**)&p_xc,  g_xc);
    cudaGetSymbolAddress((void**)&p_bcd, g_bcd);
    cudaGetSymbolAddress((void**)&p_dt,  g_dt);
    cudaGetSymbolAddress((void**)&p_o,   g_o);
    cudaGetSymbolAddress((void**)&p_hx,   h_x);
    cudaGetSymbolAddress((void**)&p_hinw, h_inw);
    cudaGetSymbolAddress((void**)&p_hxpw, h_xpw);
    cudaGetSymbolAddress((void**)&p_hdtw, h_dtw);
    cudaGetSymbolAddress((void**)&p_houtw,h_outw);
    cudaGetSymbolAddress((void**)&p_hxc,  h_xc);
    cudaGetSymbolAddress((void**)&p_hbcd, h_bcd);
    cudaGetSymbolAddress((void**)&p_hg,   h_g);

    cudaFuncSetAttribute(gemm_bf16<0,false,false,4>, cudaFuncAttributeMaxDynamicSharedMemorySize, G_SMEM_AM(4));
    cudaFuncSetAttribute(gemm_bf16<0,false,true ,4>, cudaFuncAttributeMaxDynamicSharedMemorySize, G_SMEM_AM(4));
    cudaFuncSetAttribute(gemm_bf16<1,false,false,4>, cudaFuncAttributeMaxDynamicSharedMemorySize, G_SMEM_AM(4));
    cudaFuncSetAttribute(gemm_bf16<0,true ,false,2>, cudaFuncAttributeMaxDynamicSharedMemorySize, G_SMEM_AM(2));

    // 1) fused fp32 -> bf16 converts
    cvt_all_kernel<<<(CV_S4 + 255) / 256, 256>>>(x, in_w, xp_w, dt_w, out_w,
                                                 p_hx, p_hinw, p_hxpw, p_hdtw, p_houtw);

    // 2) xz = x @ in_w^T + in_b   (2048 x 2048, K=512)
    gemm_bf16<0, false, false, 4><<<dim3((2*DI_)/G_BN, NT_/128), 256, G_SMEM_AM(4)>>>(
        p_hx, DM_, p_hinw, DM_, p_xz, 2*DI_, nullptr, 0, in_b, nullptr, NT_, 2*DI_, DM_);

    // 3) depthwise causal conv + silu + g-prepass
    conv_silu_kernel<<<(NT_*DI_/4 + 255) / 256, 256>>>(p_xz, conv_w, conv_b, D_skip,
                                                       p_xc, p_hxc, p_hg);

    // 4) bcd = x_ @ xp_w^T + xp_b   (2048 x 1056, K=1024), bf16 copy for dt GEMM
    gemm_bf16<0, false, true, 4><<<dim3((NXP_ + G_BN - 1)/G_BN, NT_/128), 256, G_SMEM_AM(4)>>>(
        p_hxc, DI_, p_hxpw, DI_, p_bcd, NXP_, p_hbcd, NXP_, xp_b, nullptr, NT_, NXP_, DI_);

    // 5) dt = softplus(bcd[:,32:] @ dt_w^T + dt_b)   (2048 x 1024, K=1024)
    gemm_bf16<1, false, false, 4><<<dim3(DI_/G_BN, NT_/128), 256, G_SMEM_AM(4)>>>(
        p_hbcd + 2*DS_, NXP_, p_hdtw, DI_, p_dt, DI_, nullptr, 0, dt_b, nullptr, NT_, DI_, DI_);

    // 6) selective scan -> overwrite g for the non-decayed prefix
    scan_kernel<<<dim3(DI_/32, B_), 512>>>(p_dt, p_xc, p_bcd, p_xz, A_log, D_skip, p_hg);

    // 7) o = g @ out_w^T + out_b + x   (2048 x 512, K=1024), BM=64 for 128 CTAs
    gemm_bf16<0, true, false, 2><<<dim3(DM_/G_BN, NT_/64), 256, G_SMEM_AM(2)>>>(
        p_hg, DI_, p_houtw, DI_, p_o, DM_, nullptr, 0, out_b, x, NT_, DM_, DI_);

    // 8) LayerNorm -> final output
    ln_kernel<<<NT_, 512>>>(p_o, ln_g, ln_b, out);
}